// round 1
// baseline (speedup 1.0000x reference)
#include <cuda_runtime.h>
#include <cstdint>
#include <math.h>

// Problem constants (fixed by setup_inputs).
#define NS   1024
#define NQ   1024
#define DDIM 128
#define HDIM 64
#define NWAY 8

// ---------------- device globals (scratch; no allocations allowed) ----------
__device__ float              g_sums[NWAY * NQ];     // [class][q]
__device__ float              g_counts[NWAY];
__device__ int                g_labels[NS];
__device__ unsigned long long g_w1p[DDIM * (HDIM / 2)];  // packed (W1[2j,d], W1[2j+1,d]) d-major

// ---------------- f32x2 helpers --------------------------------------------
__device__ __forceinline__ unsigned long long pack2f(float lo, float hi) {
    unsigned long long r;
    asm("mov.b64 %0, {%1, %2};"
        : "=l"(r) : "r"(__float_as_uint(lo)), "r"(__float_as_uint(hi)));
    return r;
}
__device__ __forceinline__ void unpack2f(unsigned long long v, float& lo, float& hi) {
    unsigned int a, b;
    asm("mov.b64 {%0, %1}, %2;" : "=r"(a), "=r"(b) : "l"(v));
    lo = __uint_as_float(a);
    hi = __uint_as_float(b);
}
__device__ __forceinline__ unsigned long long ffma2(unsigned long long a,
                                                    unsigned long long b,
                                                    unsigned long long c) {
    unsigned long long d;
    asm("fma.rn.f32x2 %0, %1, %2, %3;" : "=l"(d) : "l"(a), "l"(b), "l"(c));
    return d;
}

// ---------------- smem layout for main kernel ------------------------------
#define W1P_BYTES  (DDIM * (HDIM / 2) * 8)          // 32768
#define QS_STRIDE  129                               // pad: conflict-free scalar reads
#define TILE_BYTES (16 * QS_STRIDE * 4)              // 8256
#define QS_OFF     (W1P_BYTES)                       // 32768
#define SS_OFF     (QS_OFF + TILE_BYTES)             // 41024
#define B1_OFF     (SS_OFF + TILE_BYTES)             // 49280
#define W2_OFF     (B1_OFF + HDIM * 4)               // 49536
#define SMEM_TOTAL (W2_OFF + HDIM * 4)               // 49792

// ---------------- prep: zero sums, labels->int32, counts, pack W1 ----------
__global__ void prep_kernel(const float* __restrict__ W1, const void* __restrict__ sy_raw) {
    __shared__ int   s_is64;
    __shared__ float scnt[NWAY];
    int tid = threadIdx.x;
    if (tid == 0) s_is64 = 1;
    if (tid < NWAY) scnt[tid] = 0.0f;
    __syncthreads();

    // Detect int64 vs int32 marshalling of support_y: look at odd 32-bit words
    // of the first 512 int64-candidate slots (stays within 1024*4B either way).
    const int* sy32 = (const int*)sy_raw;
    int bad = 0;
    for (int i = tid; i < 512; i += 256)
        if (sy32[2 * i + 1] != 0) bad = 1;
    if (bad) atomicExch(&s_is64, 0);
    __syncthreads();
    int is64 = s_is64;

    const long long* sy64 = (const long long*)sy_raw;
    for (int i = tid; i < NS; i += 256) {
        int lab = is64 ? (int)sy64[i] : sy32[i];
        g_labels[i] = lab;
        atomicAdd(&scnt[lab], 1.0f);
    }
    for (int i = tid; i < NWAY * NQ; i += 256) g_sums[i] = 0.0f;

    // Pack W1 (row-major [H][D]) into d-major h-pairs.
    for (int i = tid; i < DDIM * (HDIM / 2); i += 256) {
        int d  = i >> 5;       // /32
        int j2 = i & 31;
        g_w1p[i] = pack2f(W1[(2 * j2) * DDIM + d], W1[(2 * j2 + 1) * DDIM + d]);
    }
    __syncthreads();
    if (tid < NWAY) g_counts[tid] = scnt[tid];
}

// ---------------- main: one thread per (q,s) pair --------------------------
__global__ __launch_bounds__(256, 2) void pairs_kernel(
    const float* __restrict__ qx, const float* __restrict__ sx,
    const float* __restrict__ b1, const float* __restrict__ W2,
    const float* __restrict__ b2) {
    extern __shared__ unsigned char smem[];
    unsigned long long* w1p = (unsigned long long*)smem;
    float* qs  = (float*)(smem + QS_OFF);
    float* ss  = (float*)(smem + SS_OFF);
    float* b1s = (float*)(smem + B1_OFF);
    float* w2s = (float*)(smem + W2_OFF);

    const int tid = threadIdx.x;
    const int q0  = blockIdx.x * 16;
    const int s0  = blockIdx.y * 16;

    // Stage W1 (coalesced u64 copies from prepacked global).
#pragma unroll
    for (int i = 0; i < 16; ++i) w1p[tid + 256 * i] = g_w1p[tid + 256 * i];

    // Stage q/s tiles (16 rows x 128, padded stride 129).
    for (int i = tid; i < 16 * DDIM; i += 256) {
        int r = i >> 7;        // /128
        int c = i & 127;
        qs[r * QS_STRIDE + c] = qx[(q0 + r) * DDIM + c];
        ss[r * QS_STRIDE + c] = sx[(s0 + r) * DDIM + c];
    }
    if (tid < HDIM) {
        b1s[tid] = b1[tid];
        w2s[tid] = W2[tid];
    }
    __syncthreads();

    const int tq = tid >> 4;
    const int ts = tid & 15;
    const float* qrow = qs + tq * QS_STRIDE;
    const float* srow = ss + ts * QS_STRIDE;

    unsigned long long acc[HDIM / 2];
#pragma unroll
    for (int j = 0; j < HDIM / 2; ++j) acc[j] = pack2f(b1s[2 * j], b1s[2 * j + 1]);

#pragma unroll 2
    for (int d = 0; d < DDIM; ++d) {
        float df = fabsf(qrow[d] - srow[d]);
        unsigned long long dd = pack2f(df, df);
        const ulonglong2* wrow = (const ulonglong2*)(w1p + (d << 5));
#pragma unroll
        for (int j = 0; j < 16; ++j) {
            ulonglong2 w = wrow[j];                 // LDS.128, warp-uniform broadcast
            acc[2 * j]     = ffma2(w.x, dd, acc[2 * j]);
            acc[2 * j + 1] = ffma2(w.y, dd, acc[2 * j + 1]);
        }
    }

    // Epilogue: ReLU + W2 dot + bias.
    float sim = b2[0];
#pragma unroll
    for (int j = 0; j < HDIM / 2; ++j) {
        float a0, a1;
        unpack2f(acc[j], a0, a1);
        sim += fmaxf(a0, 0.0f) * w2s[2 * j] + fmaxf(a1, 0.0f) * w2s[2 * j + 1];
    }

    int lab = g_labels[s0 + ts];
    atomicAdd(&g_sums[lab * NQ + (q0 + tq)], sim);
}

// ---------------- finalize: mean per class + log_softmax -------------------
__global__ void finalize_kernel(float* __restrict__ out) {
    int q = blockIdx.x * 256 + threadIdx.x;
    if (q >= NQ) return;
    float l[NWAY];
    float m = -1e30f;
#pragma unroll
    for (int c = 0; c < NWAY; ++c) {
        l[c] = g_sums[c * NQ + q] / g_counts[c];
        m = fmaxf(m, l[c]);
    }
    float s = 0.0f;
#pragma unroll
    for (int c = 0; c < NWAY; ++c) s += expf(l[c] - m);
    float ls = logf(s);
#pragma unroll
    for (int c = 0; c < NWAY; ++c) out[q * NWAY + c] = l[c] - m - ls;
}

// ---------------- launch ----------------------------------------------------
extern "C" void kernel_launch(void* const* d_in, const int* in_sizes, int n_in,
                              void* d_out, int out_size) {
    (void)in_sizes; (void)out_size;
    const float* support_x = (const float*)d_in[0];
    const void*  support_y = d_in[1];
    const float* query_x   = (const float*)d_in[2];
    // n_way may or may not be marshalled as an input; index weights off n_in.
    int base = (n_in >= 8) ? 4 : 3;
    const float* W1 = (const float*)d_in[base + 0];
    const float* b1 = (const float*)d_in[base + 1];
    const float* W2 = (const float*)d_in[base + 2];
    const float* b2 = (const float*)d_in[base + 3];
    float* out = (float*)d_out;

    cudaFuncSetAttribute(pairs_kernel, cudaFuncAttributeMaxDynamicSharedMemorySize,
                         SMEM_TOTAL);

    prep_kernel<<<1, 256>>>(W1, support_y);
    pairs_kernel<<<dim3(NQ / 16, NS / 16), 256, SMEM_TOTAL>>>(query_x, support_x,
                                                              b1, W2, b2);
    finalize_kernel<<<(NQ + 255) / 256, 256>>>(out);
}

// round 8
// speedup vs baseline: 6.1023x; 6.1023x over previous
#include <cuda_runtime.h>
#include <cuda_fp16.h>
#include <cstdint>
#include <math.h>

// Problem constants (fixed by setup_inputs).
#define NSUP   1024
#define NQRY   1024
#define DDIM   128
#define HDIM   64
#define NWAY   8
#define QTILE  128
#define SCHUNK 28
#define NSB    37           // ceil(1024/28), 8*37=296 CTAs = exactly 2 waves on 148 SMs

// ---------------- device scratch (no allocations allowed) -------------------
__device__ float g_sums[NWAY * NQRY];
__device__ float g_counts[NWAY];
__device__ int   g_labels[NSUP];

// ---------------- smem layout (dynamic) --------------------------------------
// A buffers: [2][kh=2][row=128][128B]  (fp16, 16B-chunk XOR swizzle per row)
#define ABUF_BYTES 32768
#define A_OFF      0                       // 2 * 32KB = 65536
#define S_OFF      65536                   // s chunk fp16: 28 rows * 256B = 7168
#define LAB_OFF    72704                   // 28 ints = 112 (pad to 128)
#define ACC_OFF    72832                   // [nj=2][class=8][q=128] f32 = 8192
#define SMEM_TOTAL 81024

// ---------------- helpers ----------------------------------------------------
__device__ __forceinline__ uint32_t saddr(const void* p) {
    uint32_t r;
    asm("{ .reg .u64 t; cvta.to.shared.u64 t, %1; cvt.u32.u64 %0, t; }"
        : "=r"(r) : "l"(p));
    return r;
}
__device__ __forceinline__ uint32_t h2u(__half2 h) {
    return *reinterpret_cast<uint32_t*>(&h);
}
__device__ __forceinline__ uint32_t hdiff2(uint32_t a, uint32_t b) {
    __half2 ha = *reinterpret_cast<__half2*>(&a);
    __half2 hb = *reinterpret_cast<__half2*>(&b);
    __half2 r  = __habs2(__hsub2(ha, hb));
    return h2u(r);
}
__device__ __forceinline__ void mma16816(float* d, uint32_t a0, uint32_t a1,
                                         uint32_t a2, uint32_t a3,
                                         uint32_t b0, uint32_t b1) {
    asm volatile(
        "mma.sync.aligned.m16n8k16.row.col.f32.f16.f16.f32 "
        "{%0,%1,%2,%3}, {%4,%5,%6,%7}, {%8,%9}, {%0,%1,%2,%3};"
        : "+f"(d[0]), "+f"(d[1]), "+f"(d[2]), "+f"(d[3])
        : "r"(a0), "r"(a1), "r"(a2), "r"(a3), "r"(b0), "r"(b1));
}

// ---------------- prep: labels, counts, zero sums ----------------------------
__global__ void prep_kernel(const void* __restrict__ sy_raw) {
    __shared__ int   s_is64;
    __shared__ float scnt[NWAY];
    int tid = threadIdx.x;
    if (tid == 0) s_is64 = 1;
    if (tid < NWAY) scnt[tid] = 0.0f;
    __syncthreads();

    // Detect int64 vs int32 marshalling of support_y (odd words all zero => int64).
    const int* sy32 = (const int*)sy_raw;
    int bad = 0;
    for (int i = tid; i < 512; i += 256)
        if (sy32[2 * i + 1] != 0) bad = 1;
    if (bad) atomicExch(&s_is64, 0);
    __syncthreads();
    int is64 = s_is64;

    const long long* sy64 = (const long long*)sy_raw;
    for (int i = tid; i < NSUP; i += 256) {
        int lab = is64 ? (int)sy64[i] : sy32[i];
        g_labels[i] = lab;
        atomicAdd(&scnt[lab], 1.0f);
    }
    for (int i = tid; i < NWAY * NQRY; i += 256) g_sums[i] = 0.0f;
    __syncthreads();
    if (tid < NWAY) g_counts[tid] = scnt[tid];
}

// ---------------- main kernel ------------------------------------------------
__global__ __launch_bounds__(256, 1) void pairs_kernel(
    const float* __restrict__ qx, const float* __restrict__ sx,
    const float* __restrict__ W1, const float* __restrict__ b1,
    const float* __restrict__ w2v) {
    extern __shared__ char smem[];
    const int tid  = threadIdx.x;
    const int lane = tid & 31;
    const int wid  = tid >> 5;
    const int mi   = wid & 3;          // warp m-slice (32 rows)
    const int nj   = wid >> 2;         // warp n-slice (32 cols)
    const int q0   = blockIdx.x * QTILE;
    const int s0   = blockIdx.y * SCHUNK;
    const int ns   = min(SCHUNK, NSUP - s0);
    const uint32_t sbase = saddr(smem);

    // ---- stage s chunk as fp16 (row = 256B), labels, zero acc ----
    __half2* s_sm = (__half2*)(smem + S_OFF);
    for (int idx = tid; idx < ns * 64; idx += 256) {
        int r = idx >> 6, c = idx & 63;
        float2 v = *(const float2*)(sx + (size_t)(s0 + r) * DDIM + 2 * c);
        s_sm[idx] = __floats2half2_rn(v.x, v.y);
    }
    int* slab = (int*)(smem + LAB_OFF);
    for (int idx = tid; idx < ns; idx += 256) slab[idx] = g_labels[s0 + idx];
    float* accf = (float*)(smem + ACC_OFF);
    for (int idx = tid; idx < 2 * NWAY * QTILE; idx += 256) accf[idx] = 0.0f;

    // ---- q row in registers as fp16x2: thread owns (m, kh) -> 64 values ----
    const int m  = tid & 127;
    const int kh = tid >> 7;
    uint4 qv[8];
    {
        const float4* qp = (const float4*)(qx + (size_t)(q0 + m) * DDIM + kh * 64);
#pragma unroll
        for (int j = 0; j < 8; ++j) {
            float4 f0 = qp[2 * j], f1 = qp[2 * j + 1];
            qv[j].x = h2u(__floats2half2_rn(f0.x, f0.y));
            qv[j].y = h2u(__floats2half2_rn(f0.z, f0.w));
            qv[j].z = h2u(__floats2half2_rn(f1.x, f1.y));
            qv[j].w = h2u(__floats2half2_rn(f1.z, f1.w));
        }
    }

    // ---- W1 fragments in registers (fp16), warp covers n-slice nj*32..+31 ----
    // B frag (n8 x k16) per (nb, kb): b0 holds k=(lane%4)*2,+1; b1 holds k+8,+9.
    uint32_t Bf[4][8][2];
#pragma unroll
    for (int nb = 0; nb < 4; ++nb) {
        int n = nj * 32 + nb * 8 + (lane >> 2);
        const float* wr = W1 + n * DDIM;
#pragma unroll
        for (int kb = 0; kb < 8; ++kb) {
            int k = kb * 16 + (lane & 3) * 2;
            Bf[nb][kb][0] = h2u(__floats2half2_rn(wr[k], wr[k + 1]));
            Bf[nb][kb][1] = h2u(__floats2half2_rn(wr[k + 8], wr[k + 9]));
        }
    }

    // ---- b1 / w2 for this thread's output columns ----
    float b1r[8], w2r[8];
#pragma unroll
    for (int nb = 0; nb < 4; ++nb)
#pragma unroll
        for (int c = 0; c < 2; ++c) {
            int col = nj * 32 + nb * 8 + (lane & 3) * 2 + c;
            b1r[nb * 2 + c] = b1[col];
            w2r[nb * 2 + c] = w2v[col];
        }

    __syncthreads();   // s_sm staged

    // ---- A tile generation: thread writes row m, half kh (64 fp16 = 8x16B) ----
    auto gen_tile = [&](int buf, int i) {
        const uint4* sp = (const uint4*)((const char*)smem + S_OFF + i * 256 + kh * 128);
        char* base = smem + A_OFF + buf * ABUF_BYTES + kh * 16384 + m * 128;
        const int X = m & 7;
#pragma unroll
        for (int j = 0; j < 8; ++j) {
            uint4 sv = sp[j];
            uint4 o;
            o.x = hdiff2(qv[j].x, sv.x);
            o.y = hdiff2(qv[j].y, sv.y);
            o.z = hdiff2(qv[j].z, sv.z);
            o.w = hdiff2(qv[j].w, sv.w);
            *(uint4*)(base + ((j ^ X) << 4)) = o;
        }
    };

    gen_tile(0, 0);
    __syncthreads();   // A[0] ready

    // ldmatrix row/lane geometry (constant per thread)
    const int lrow_in16 = lane & 15;       // row within m16 block
    const int ljk       = lane >> 4;       // 0: k 0-7, 1: k 8-15
    const int lxr       = lane & 7;        // XOR key (row & 7)

    for (int i = 0; i < ns; ++i) {
        const int buf = i & 1;
        float D[2][4][4];
#pragma unroll
        for (int mb = 0; mb < 2; ++mb)
#pragma unroll
            for (int nb = 0; nb < 4; ++nb)
#pragma unroll
                for (int c = 0; c < 4; ++c) D[mb][nb][c] = 0.0f;

#pragma unroll
        for (int mb = 0; mb < 2; ++mb) {
            const int r = mi * 32 + mb * 16 + lrow_in16;
            const uint32_t rowb = sbase + A_OFF + buf * ABUF_BYTES + r * 128;
#pragma unroll
            for (int kb = 0; kb < 8; ++kb) {
                const int c16  = (kb & 3) * 2 + ljk;
                const uint32_t addr = rowb + ((kb >> 2) * 16384) + (((c16 ^ lxr)) << 4);
                uint32_t a0, a1, a2, a3;
                asm volatile(
                    "ldmatrix.sync.aligned.m8n8.x4.shared.b16 {%0,%1,%2,%3}, [%4];"
                    : "=r"(a0), "=r"(a1), "=r"(a2), "=r"(a3) : "r"(addr));
#pragma unroll
                for (int nb = 0; nb < 4; ++nb)
                    mma16816(D[mb][nb], a0, a1, a2, a3, Bf[nb][kb][0], Bf[nb][kb][1]);
            }
        }

        // Overlap: generate next A tile while HMMAs drain.
        if (i + 1 < ns) gen_tile(buf ^ 1, i + 1);

        // Epilogue: relu(h + b1) . w2 for this warp's (m32 x n32) slice.
        const int lab = slab[i];
#pragma unroll
        for (int mb = 0; mb < 2; ++mb) {
            float p0 = 0.0f, p1 = 0.0f;
#pragma unroll
            for (int nb = 0; nb < 4; ++nb)
#pragma unroll
                for (int c = 0; c < 2; ++c) {
                    p0 = fmaf(fmaxf(D[mb][nb][c]     + b1r[nb * 2 + c], 0.0f), w2r[nb * 2 + c], p0);
                    p1 = fmaf(fmaxf(D[mb][nb][2 + c] + b1r[nb * 2 + c], 0.0f), w2r[nb * 2 + c], p1);
                }
            p0 += __shfl_xor_sync(0xffffffffu, p0, 1);
            p0 += __shfl_xor_sync(0xffffffffu, p0, 2);
            p1 += __shfl_xor_sync(0xffffffffu, p1, 1);
            p1 += __shfl_xor_sync(0xffffffffu, p1, 2);
            if ((lane & 3) == 0) {
                int r0 = mi * 32 + mb * 16 + (lane >> 2);
                accf[nj * (NWAY * QTILE) + lab * QTILE + r0]     += p0;
                accf[nj * (NWAY * QTILE) + lab * QTILE + r0 + 8] += p1;
            }
        }
        __syncthreads();   // A[buf^1] writes visible; acc iteration complete
    }

    // Flush per-CTA class sums (merge the two n-halves).
    for (int idx = tid; idx < NWAY * QTILE; idx += 256)
        atomicAdd(&g_sums[(idx >> 7) * NQRY + q0 + (idx & 127)],
                  accf[idx] + accf[NWAY * QTILE + idx]);
}

// ---------------- finalize: mean per class + b2 + log_softmax ----------------
__global__ void finalize_kernel(float* __restrict__ out, const float* __restrict__ b2) {
    int q = blockIdx.x * 256 + threadIdx.x;
    if (q >= NQRY) return;
    float bb = b2[0];
    float l[NWAY];
    float mx = -1e30f;
#pragma unroll
    for (int c = 0; c < NWAY; ++c) {
        l[c] = g_sums[c * NQRY + q] / g_counts[c] + bb;
        mx = fmaxf(mx, l[c]);
    }
    float s = 0.0f;
#pragma unroll
    for (int c = 0; c < NWAY; ++c) s += expf(l[c] - mx);
    float ls = logf(s);
#pragma unroll
    for (int c = 0; c < NWAY; ++c) out[q * NWAY + c] = l[c] - mx - ls;
}

// ---------------- launch ------------------------------------------------------
extern "C" void kernel_launch(void* const* d_in, const int* in_sizes, int n_in,
                              void* d_out, int out_size) {
    (void)in_sizes; (void)out_size;
    const float* support_x = (const float*)d_in[0];
    const void*  support_y = d_in[1];
    const float* query_x   = (const float*)d_in[2];
    int base = (n_in >= 8) ? 4 : 3;   // n_way scalar may or may not be marshalled
    const float* W1 = (const float*)d_in[base + 0];
    const float* b1 = (const float*)d_in[base + 1];
    const float* W2 = (const float*)d_in[base + 2];
    const float* b2 = (const float*)d_in[base + 3];
    float* out = (float*)d_out;

    cudaFuncSetAttribute(pairs_kernel, cudaFuncAttributeMaxDynamicSharedMemorySize,
                         SMEM_TOTAL);

    prep_kernel<<<1, 256>>>(support_y);
    pairs_kernel<<<dim3(NQRY / QTILE, NSB), 256, SMEM_TOTAL>>>(query_x, support_x,
                                                               W1, b1, W2);
    finalize_kernel<<<(NQRY + 255) / 256, 256>>>(out, b2);
}

// round 9
// speedup vs baseline: 7.0143x; 1.1495x over previous
#include <cuda_runtime.h>
#include <cuda_fp16.h>
#include <cstdint>
#include <math.h>

// Problem constants (fixed by setup_inputs).
#define NSUP   1024
#define NQRY   1024
#define DDIM   128
#define HDIM   64
#define NWAY   8
#define QTILE  128
#define SCHUNK 28
#define NSB    37           // ceil(1024/28); grid 8 x 37 = 296 = exactly 2 waves

// Per-CTA partial sums: [qb*NSB + sb][class][q] -- fully written, no init needed.
__device__ float g_part[(NQRY / QTILE) * NSB * NWAY * QTILE];

// ---------------- helpers ----------------------------------------------------
__device__ __forceinline__ uint32_t h2u(__half2 h) {
    return *reinterpret_cast<uint32_t*>(&h);
}
__device__ __forceinline__ uint32_t absdiff2(uint32_t q, __half2 s) {
    __half2 hq = *reinterpret_cast<__half2*>(&q);
    return h2u(__habs2(__hsub2(hq, s)));
}
__device__ __forceinline__ void mma16816(float* d, uint32_t a0, uint32_t a1,
                                         uint32_t a2, uint32_t a3,
                                         uint32_t b0, uint32_t b1) {
    asm volatile(
        "mma.sync.aligned.m16n8k16.row.col.f32.f16.f16.f32 "
        "{%0,%1,%2,%3}, {%4,%5,%6,%7}, {%8,%9}, {%0,%1,%2,%3};"
        : "+f"(d[0]), "+f"(d[1]), "+f"(d[2]), "+f"(d[3])
        : "r"(a0), "r"(a1), "r"(a2), "r"(a3), "r"(b0), "r"(b1));
}

// ---------------- main kernel -------------------------------------------------
// CTA: 128-q block x 28-s chunk. Warp (mi, nj): mi = 32-row m-slice, nj = 32-col
// n-slice. A fragments are computed directly in registers (no smem A, no
// ldmatrix): thread owns q rows mi*32 + (lane>>2) + {0,8,16,24} at the exact
// k-columns its mma fragments need.
__global__ __launch_bounds__(256, 1) void pairs_kernel(
    const float* __restrict__ qx, const float* __restrict__ sx,
    const float* __restrict__ W1, const float* __restrict__ b1,
    const float* __restrict__ w2v, const void* __restrict__ sy_raw) {
    __shared__ __half2 s_sm[SCHUNK * 64];          // s chunk, fp16x2
    __shared__ float   accf[2 * NWAY * QTILE];     // [nj][class][q]
    __shared__ int     slab[SCHUNK];
    __shared__ int     s_is64;

    const int tid  = threadIdx.x;
    const int lane = tid & 31;
    const int wid  = tid >> 5;
    const int mi   = wid & 3;
    const int nj   = wid >> 2;
    const int g    = lane >> 2;       // row-in-8 group
    const int i2   = lane & 3;        // k quad position
    const int q0   = blockIdx.x * QTILE;
    const int s0   = blockIdx.y * SCHUNK;
    const int ns   = min(SCHUNK, NSUP - s0);

    if (tid == 0) s_is64 = 1;
    for (int idx = tid; idx < 2 * NWAY * QTILE; idx += 256) accf[idx] = 0.0f;
    __syncthreads();

    // int64-vs-int32 detection for support_y (odd words all zero => int64).
    const int* sy32 = (const int*)sy_raw;
    if (sy32[2 * tid + 1] != 0) atomicExch(&s_is64, 0);

    // Stage s chunk as half2 (row = 64 half2 = 256B).
    for (int idx = tid; idx < ns * 64; idx += 256) {
        int r = idx >> 6, c = idx & 63;
        float2 v = *(const float2*)(sx + (size_t)(s0 + r) * DDIM + 2 * c);
        s_sm[idx] = __floats2half2_rn(v.x, v.y);
    }
    __syncthreads();

    const int is64 = s_is64;
    const long long* sy64 = (const long long*)sy_raw;
    if (tid < ns) slab[tid] = is64 ? (int)sy64[s0 + tid] : sy32[s0 + tid];

    // ---- q fragment values in registers: qh[ri][kb][h] ----
    // ri 0..3 -> q row q0 + mi*32 + g + ri*8; h=0 -> cols k0,k0+1; h=1 -> k0+8,k0+9
    uint32_t qh[4][8][2];
#pragma unroll
    for (int ri = 0; ri < 4; ++ri) {
        const float* qp = qx + (size_t)(q0 + mi * 32 + g + ri * 8) * DDIM + i2 * 2;
#pragma unroll
        for (int kb = 0; kb < 8; ++kb) {
            float2 v0 = *(const float2*)(qp + kb * 16);
            float2 v1 = *(const float2*)(qp + kb * 16 + 8);
            qh[ri][kb][0] = h2u(__floats2half2_rn(v0.x, v0.y));
            qh[ri][kb][1] = h2u(__floats2half2_rn(v1.x, v1.y));
        }
    }

    // ---- W1 B-fragments in registers (warp covers cols nj*32..+31) ----
    uint32_t Bf[4][8][2];
#pragma unroll
    for (int nb = 0; nb < 4; ++nb) {
        const float* wr = W1 + (size_t)(nj * 32 + nb * 8 + g) * DDIM + i2 * 2;
#pragma unroll
        for (int kb = 0; kb < 8; ++kb) {
            float2 v0 = *(const float2*)(wr + kb * 16);
            float2 v1 = *(const float2*)(wr + kb * 16 + 8);
            Bf[nb][kb][0] = h2u(__floats2half2_rn(v0.x, v0.y));
            Bf[nb][kb][1] = h2u(__floats2half2_rn(v1.x, v1.y));
        }
    }

    // ---- b1 / w2 for this thread's output columns ----
    float b1r[8], w2r[8];
#pragma unroll
    for (int nb = 0; nb < 4; ++nb)
#pragma unroll
        for (int c = 0; c < 2; ++c) {
            int col = nj * 32 + nb * 8 + i2 * 2 + c;
            b1r[nb * 2 + c] = b1[col];
            w2r[nb * 2 + c] = w2v[col];
        }

    __syncthreads();   // slab ready (s_sm already synced)

    // ---- main loop: one s row per iteration; no barriers inside ----
    for (int i = 0; i < ns; ++i) {
        const __half2* srow = s_sm + i * 64;

        // D init = b1 (d0,d1: row g; d2,d3: row g+8 -> same columns/bias).
        float D[2][4][4];
#pragma unroll
        for (int mb = 0; mb < 2; ++mb)
#pragma unroll
            for (int nb = 0; nb < 4; ++nb) {
                D[mb][nb][0] = b1r[nb * 2];
                D[mb][nb][1] = b1r[nb * 2 + 1];
                D[mb][nb][2] = b1r[nb * 2];
                D[mb][nb][3] = b1r[nb * 2 + 1];
            }

#pragma unroll
        for (int kb = 0; kb < 8; ++kb) {
            __half2 hs0 = srow[kb * 8 + i2];          // s[k0], s[k0+1]
            __half2 hs1 = srow[kb * 8 + 4 + i2];      // s[k0+8], s[k0+9]
#pragma unroll
            for (int mb = 0; mb < 2; ++mb) {
                uint32_t a0 = absdiff2(qh[2 * mb][kb][0], hs0);
                uint32_t a1 = absdiff2(qh[2 * mb + 1][kb][0], hs0);
                uint32_t a2 = absdiff2(qh[2 * mb][kb][1], hs1);
                uint32_t a3 = absdiff2(qh[2 * mb + 1][kb][1], hs1);
#pragma unroll
                for (int nb = 0; nb < 4; ++nb)
                    mma16816(D[mb][nb], a0, a1, a2, a3, Bf[nb][kb][0], Bf[nb][kb][1]);
            }
        }

        // Epilogue: sim contribution = sum_n relu(h) * w2 for this warp slice.
        const int lab = slab[i];
#pragma unroll
        for (int mb = 0; mb < 2; ++mb) {
            float p0 = 0.0f, p1 = 0.0f;
#pragma unroll
            for (int nb = 0; nb < 4; ++nb)
#pragma unroll
                for (int c = 0; c < 2; ++c) {
                    p0 = fmaf(fmaxf(D[mb][nb][c],     0.0f), w2r[nb * 2 + c], p0);
                    p1 = fmaf(fmaxf(D[mb][nb][2 + c], 0.0f), w2r[nb * 2 + c], p1);
                }
            p0 += __shfl_xor_sync(0xffffffffu, p0, 1);
            p0 += __shfl_xor_sync(0xffffffffu, p0, 2);
            p1 += __shfl_xor_sync(0xffffffffu, p1, 1);
            p1 += __shfl_xor_sync(0xffffffffu, p1, 2);
            if (i2 == 0) {
                int r0 = mi * 32 + mb * 16 + g;      // unique (warp,g) -> row
                accf[nj * (NWAY * QTILE) + lab * QTILE + r0]     += p0;
                accf[nj * (NWAY * QTILE) + lab * QTILE + r0 + 8] += p1;
            }
        }
    }

    __syncthreads();
    // Flush per-CTA partials (merge n-halves); unique g_part slice per CTA.
    float* dst = g_part + (size_t)(blockIdx.x * NSB + blockIdx.y) * (NWAY * QTILE);
    for (int idx = tid; idx < NWAY * QTILE; idx += 256)
        dst[idx] = accf[idx] + accf[NWAY * QTILE + idx];
}

// ---------------- finalize: reduce partials, counts, mean, log_softmax -------
__global__ void finalize_kernel(float* __restrict__ out, const float* __restrict__ b2,
                                const void* __restrict__ sy_raw) {
    __shared__ float scnt[NWAY];
    __shared__ int   s_is64;
    const int tid = threadIdx.x;
    const int q   = blockIdx.x * 256 + tid;
    if (tid == 0) s_is64 = 1;
    if (tid < NWAY) scnt[tid] = 0.0f;
    __syncthreads();

    const int* sy32 = (const int*)sy_raw;
    if (sy32[2 * tid + 1] != 0 || sy32[2 * (tid + 256) + 1] != 0)
        atomicExch(&s_is64, 0);
    __syncthreads();
    const int is64 = s_is64;
    const long long* sy64 = (const long long*)sy_raw;
    for (int i = tid; i < NSUP; i += 256) {
        int lab = is64 ? (int)sy64[i] : sy32[i];
        atomicAdd(&scnt[lab], 1.0f);
    }
    __syncthreads();

    const int qb = q >> 7, qi = q & 127;
    float acc[NWAY];
#pragma unroll
    for (int c = 0; c < NWAY; ++c) acc[c] = 0.0f;
    for (int sb = 0; sb < NSB; ++sb) {
        const float* p = g_part + (size_t)(qb * NSB + sb) * (NWAY * QTILE) + qi;
#pragma unroll
        for (int c = 0; c < NWAY; ++c) acc[c] += p[c * QTILE];
    }

    const float bb = b2[0];
    float l[NWAY], mx = -1e30f;
#pragma unroll
    for (int c = 0; c < NWAY; ++c) {
        l[c] = acc[c] / scnt[c] + bb;
        mx = fmaxf(mx, l[c]);
    }
    float s = 0.0f;
#pragma unroll
    for (int c = 0; c < NWAY; ++c) s += expf(l[c] - mx);
    const float ls = logf(s);
#pragma unroll
    for (int c = 0; c < NWAY; ++c) out[q * NWAY + c] = l[c] - mx - ls;
}

// ---------------- launch --------------------------------------------------------
extern "C" void kernel_launch(void* const* d_in, const int* in_sizes, int n_in,
                              void* d_out, int out_size) {
    (void)in_sizes; (void)out_size;
    const float* support_x = (const float*)d_in[0];
    const void*  support_y = d_in[1];
    const float* query_x   = (const float*)d_in[2];
    int base = (n_in >= 8) ? 4 : 3;   // n_way scalar may or may not be marshalled
    const float* W1 = (const float*)d_in[base + 0];
    const float* b1 = (const float*)d_in[base + 1];
    const float* W2 = (const float*)d_in[base + 2];
    const float* b2 = (const float*)d_in[base + 3];
    float* out = (float*)d_out;

    pairs_kernel<<<dim3(NQRY / QTILE, NSB), 256>>>(query_x, support_x, W1, b1, W2,
                                                   support_y);
    finalize_kernel<<<NQRY / 256, 256>>>(out, b2, support_y);
}

// round 10
// speedup vs baseline: 8.3582x; 1.1916x over previous
#include <cuda_runtime.h>
#include <cuda_fp16.h>
#include <cstdint>
#include <math.h>

// Problem constants (fixed by setup_inputs).
#define NSUP   1024
#define NQRY   1024
#define DDIM   128
#define HDIM   64
#define NWAY   8
#define QTILE  128
#define SCHUNK 28
#define NSB    37           // ceil(1024/28); grid 8 x 37 = 296 = exactly 2 waves

// Per-CTA partial sums: [qb*NSB + sb][class][q] -- fully written, no init needed.
__device__ float g_part[(NQRY / QTILE) * NSB * NWAY * QTILE];

// ---------------- helpers ----------------------------------------------------
__device__ __forceinline__ uint32_t h2u(__half2 h) {
    return *reinterpret_cast<uint32_t*>(&h);
}
__device__ __forceinline__ uint32_t absdiff2(uint32_t q, __half2 s) {
    __half2 hq = *reinterpret_cast<__half2*>(&q);
    return h2u(__habs2(__hsub2(hq, s)));
}
__device__ __forceinline__ void mma16816(float* d, uint32_t a0, uint32_t a1,
                                         uint32_t a2, uint32_t a3,
                                         uint32_t b0, uint32_t b1) {
    asm volatile(
        "mma.sync.aligned.m16n8k16.row.col.f32.f16.f16.f32 "
        "{%0,%1,%2,%3}, {%4,%5,%6,%7}, {%8,%9}, {%0,%1,%2,%3};"
        : "+f"(d[0]), "+f"(d[1]), "+f"(d[2]), "+f"(d[3])
        : "r"(a0), "r"(a1), "r"(a2), "r"(a3), "r"(b0), "r"(b1));
}

// ---------------- main kernel -------------------------------------------------
// CTA: 128-q block x 28-s chunk. Warp (mi, nj): mi = 32-row m-slice, nj = 32-col
// n-slice. A fragments are computed directly in registers (no smem A, no
// ldmatrix): thread owns q rows mi*32 + (lane>>2) + {0,8,16,24} at the exact
// k-columns its mma fragments need.
__global__ __launch_bounds__(256, 1) void pairs_kernel(
    const float* __restrict__ qx, const float* __restrict__ sx,
    const float* __restrict__ W1, const float* __restrict__ b1,
    const float* __restrict__ w2v, const void* __restrict__ sy_raw) {
    __shared__ __half2 s_sm[SCHUNK * 64];          // s chunk, fp16x2
    __shared__ float   accf[2 * NWAY * QTILE];     // [nj][class][q]
    __shared__ int     slab[SCHUNK];
    __shared__ int     s_is64;

    const int tid  = threadIdx.x;
    const int lane = tid & 31;
    const int wid  = tid >> 5;
    const int mi   = wid & 3;
    const int nj   = wid >> 2;
    const int g    = lane >> 2;       // row-in-8 group
    const int i2   = lane & 3;        // k quad position
    const int q0   = blockIdx.x * QTILE;
    const int s0   = blockIdx.y * SCHUNK;
    const int ns   = min(SCHUNK, NSUP - s0);

    if (tid == 0) s_is64 = 1;
    for (int idx = tid; idx < 2 * NWAY * QTILE; idx += 256) accf[idx] = 0.0f;
    __syncthreads();

    // int64-vs-int32 detection for support_y (odd words all zero => int64).
    const int* sy32 = (const int*)sy_raw;
    if (sy32[2 * tid + 1] != 0) atomicExch(&s_is64, 0);

    // Stage s chunk as half2 (row = 64 half2 = 256B).
    for (int idx = tid; idx < ns * 64; idx += 256) {
        int r = idx >> 6, c = idx & 63;
        float2 v = *(const float2*)(sx + (size_t)(s0 + r) * DDIM + 2 * c);
        s_sm[idx] = __floats2half2_rn(v.x, v.y);
    }
    __syncthreads();

    const int is64 = s_is64;
    const long long* sy64 = (const long long*)sy_raw;
    if (tid < ns) slab[tid] = is64 ? (int)sy64[s0 + tid] : sy32[s0 + tid];

    // ---- q fragment values in registers: qh[ri][kb][h] ----
    // ri 0..3 -> q row q0 + mi*32 + g + ri*8; h=0 -> cols k0,k0+1; h=1 -> k0+8,k0+9
    uint32_t qh[4][8][2];
#pragma unroll
    for (int ri = 0; ri < 4; ++ri) {
        const float* qp = qx + (size_t)(q0 + mi * 32 + g + ri * 8) * DDIM + i2 * 2;
#pragma unroll
        for (int kb = 0; kb < 8; ++kb) {
            float2 v0 = *(const float2*)(qp + kb * 16);
            float2 v1 = *(const float2*)(qp + kb * 16 + 8);
            qh[ri][kb][0] = h2u(__floats2half2_rn(v0.x, v0.y));
            qh[ri][kb][1] = h2u(__floats2half2_rn(v1.x, v1.y));
        }
    }

    // ---- W1 B-fragments in registers (warp covers cols nj*32..+31) ----
    uint32_t Bf[4][8][2];
#pragma unroll
    for (int nb = 0; nb < 4; ++nb) {
        const float* wr = W1 + (size_t)(nj * 32 + nb * 8 + g) * DDIM + i2 * 2;
#pragma unroll
        for (int kb = 0; kb < 8; ++kb) {
            float2 v0 = *(const float2*)(wr + kb * 16);
            float2 v1 = *(const float2*)(wr + kb * 16 + 8);
            Bf[nb][kb][0] = h2u(__floats2half2_rn(v0.x, v0.y));
            Bf[nb][kb][1] = h2u(__floats2half2_rn(v1.x, v1.y));
        }
    }

    // ---- b1 / w2 for this thread's output columns ----
    float b1r[8], w2r[8];
#pragma unroll
    for (int nb = 0; nb < 4; ++nb)
#pragma unroll
        for (int c = 0; c < 2; ++c) {
            int col = nj * 32 + nb * 8 + i2 * 2 + c;
            b1r[nb * 2 + c] = b1[col];
            w2r[nb * 2 + c] = w2v[col];
        }

    __syncthreads();   // slab ready (s_sm already synced)

    // ---- main loop: one s row per iteration; no barriers inside ----
    for (int i = 0; i < ns; ++i) {
        const __half2* srow = s_sm + i * 64;

        // D init = b1 (d0,d1: row g; d2,d3: row g+8 -> same columns/bias).
        float D[2][4][4];
#pragma unroll
        for (int mb = 0; mb < 2; ++mb)
#pragma unroll
            for (int nb = 0; nb < 4; ++nb) {
                D[mb][nb][0] = b1r[nb * 2];
                D[mb][nb][1] = b1r[nb * 2 + 1];
                D[mb][nb][2] = b1r[nb * 2];
                D[mb][nb][3] = b1r[nb * 2 + 1];
            }

#pragma unroll
        for (int kb = 0; kb < 8; ++kb) {
            __half2 hs0 = srow[kb * 8 + i2];          // s[k0], s[k0+1]
            __half2 hs1 = srow[kb * 8 + 4 + i2];      // s[k0+8], s[k0+9]
#pragma unroll
            for (int mb = 0; mb < 2; ++mb) {
                uint32_t a0 = absdiff2(qh[2 * mb][kb][0], hs0);
                uint32_t a1 = absdiff2(qh[2 * mb + 1][kb][0], hs0);
                uint32_t a2 = absdiff2(qh[2 * mb][kb][1], hs1);
                uint32_t a3 = absdiff2(qh[2 * mb + 1][kb][1], hs1);
#pragma unroll
                for (int nb = 0; nb < 4; ++nb)
                    mma16816(D[mb][nb], a0, a1, a2, a3, Bf[nb][kb][0], Bf[nb][kb][1]);
            }
        }

        // Epilogue: sim contribution = sum_n relu(h) * w2 for this warp slice.
        const int lab = slab[i];
#pragma unroll
        for (int mb = 0; mb < 2; ++mb) {
            float p0 = 0.0f, p1 = 0.0f;
#pragma unroll
            for (int nb = 0; nb < 4; ++nb)
#pragma unroll
                for (int c = 0; c < 2; ++c) {
                    p0 = fmaf(fmaxf(D[mb][nb][c],     0.0f), w2r[nb * 2 + c], p0);
                    p1 = fmaf(fmaxf(D[mb][nb][2 + c], 0.0f), w2r[nb * 2 + c], p1);
                }
            p0 += __shfl_xor_sync(0xffffffffu, p0, 1);
            p0 += __shfl_xor_sync(0xffffffffu, p0, 2);
            p1 += __shfl_xor_sync(0xffffffffu, p1, 1);
            p1 += __shfl_xor_sync(0xffffffffu, p1, 2);
            if (i2 == 0) {
                int r0 = mi * 32 + mb * 16 + g;      // unique (warp,g) -> row
                accf[nj * (NWAY * QTILE) + lab * QTILE + r0]     += p0;
                accf[nj * (NWAY * QTILE) + lab * QTILE + r0 + 8] += p1;
            }
        }
    }

    __syncthreads();
    // Flush per-CTA partials (merge n-halves); unique g_part slice per CTA.
    float* dst = g_part + (size_t)(blockIdx.x * NSB + blockIdx.y) * (NWAY * QTILE);
    for (int idx = tid; idx < NWAY * QTILE; idx += 256)
        dst[idx] = accf[idx] + accf[NWAY * QTILE + idx];
}

// ---------------- finalize: parallel reduce + counts + log_softmax -----------
// 32 CTAs x 256 threads: one thread per (q, class). tid = c*32 + qi_local so a
// warp's loads over qi are coalesced. Softmax via 32x8 smem transpose.
__global__ __launch_bounds__(256, 4) void finalize_kernel(
    float* __restrict__ out, const float* __restrict__ b2,
    const void* __restrict__ sy_raw) {
    __shared__ float s_l[32 * NWAY];
    __shared__ float s_cnt[NWAY];
    __shared__ int   s_is64;

    const int tid = threadIdx.x;
    const int lane = tid & 31;
    const int wid = tid >> 5;
    const int c        = tid >> 5;            // class 0..7 (== wid)
    const int qi_local = tid & 31;
    const int q = blockIdx.x * 32 + qi_local; // q index 0..1023
    const int qb = q >> 7, qi = q & 127;

    if (tid == 0) s_is64 = 1;
    __syncthreads();
    const int* sy32 = (const int*)sy_raw;
    if (sy32[2 * tid + 1] != 0 || sy32[2 * (tid + 256) + 1] != 0)
        atomicExch(&s_is64, 0);
    __syncthreads();

    // Warp 0: register-local label histogram (32 labels/lane), shfl-reduce.
    if (wid == 0) {
        const int is64 = s_is64;
        const long long* sy64 = (const long long*)sy_raw;
        float cnt[NWAY];
#pragma unroll
        for (int k = 0; k < NWAY; ++k) cnt[k] = 0.0f;
        for (int i = lane; i < NSUP; i += 32) {
            int lab = is64 ? (int)sy64[i] : sy32[i];
#pragma unroll
            for (int k = 0; k < NWAY; ++k) cnt[k] += (lab == k) ? 1.0f : 0.0f;
        }
#pragma unroll
        for (int k = 0; k < NWAY; ++k) {
            cnt[k] += __shfl_xor_sync(0xffffffffu, cnt[k], 16);
            cnt[k] += __shfl_xor_sync(0xffffffffu, cnt[k], 8);
            cnt[k] += __shfl_xor_sync(0xffffffffu, cnt[k], 4);
            cnt[k] += __shfl_xor_sync(0xffffffffu, cnt[k], 2);
            cnt[k] += __shfl_xor_sync(0xffffffffu, cnt[k], 1);
        }
        if (lane < NWAY) s_cnt[lane] = cnt[lane];
    }

    // Reduce 37 partials for this (q, c); coalesced across the warp.
    float acc = 0.0f;
    const float* p = g_part + ((size_t)(qb * NSB) * NWAY + c) * QTILE + qi;
#pragma unroll 4
    for (int sb = 0; sb < NSB; ++sb) acc += p[(size_t)sb * (NWAY * QTILE)];

    __syncthreads();
    s_l[qi_local * NWAY + c] = acc / s_cnt[c] + b2[0];
    __syncthreads();

    // Threads 0..31: softmax for one q each.
    if (tid < 32) {
        float l[NWAY], mx = -1e30f;
#pragma unroll
        for (int k = 0; k < NWAY; ++k) {
            l[k] = s_l[tid * NWAY + k];
            mx = fmaxf(mx, l[k]);
        }
        float s = 0.0f;
#pragma unroll
        for (int k = 0; k < NWAY; ++k) s += expf(l[k] - mx);
        const float ls = logf(s);
        float* o = out + (size_t)(blockIdx.x * 32 + tid) * NWAY;
#pragma unroll
        for (int k = 0; k < NWAY; ++k) o[k] = l[k] - mx - ls;
    }
}

// ---------------- launch --------------------------------------------------------
extern "C" void kernel_launch(void* const* d_in, const int* in_sizes, int n_in,
                              void* d_out, int out_size) {
    (void)in_sizes; (void)out_size;
    const float* support_x = (const float*)d_in[0];
    const void*  support_y = d_in[1];
    const float* query_x   = (const float*)d_in[2];
    int base = (n_in >= 8) ? 4 : 3;   // n_way scalar may or may not be marshalled
    const float* W1 = (const float*)d_in[base + 0];
    const float* b1 = (const float*)d_in[base + 1];
    const float* W2 = (const float*)d_in[base + 2];
    const float* b2 = (const float*)d_in[base + 3];
    float* out = (float*)d_out;

    pairs_kernel<<<dim3(NQRY / QTILE, NSB), 256>>>(query_x, support_x, W1, b1, W2,
                                                   support_y);
    finalize_kernel<<<NQRY / 32, 256>>>(out, b2, support_y);
}

// round 11
// speedup vs baseline: 8.6346x; 1.0331x over previous
#include <cuda_runtime.h>
#include <cuda_fp16.h>
#include <cstdint>
#include <math.h>

// Problem constants (fixed by setup_inputs).
#define NSUP   1024
#define NQRY   1024
#define DDIM   128
#define HDIM   64
#define NWAY   8
#define QTILE  128
#define SCHUNK 28
#define NSB    37           // ceil(1024/28); grid 8 x 37 = 296 = exactly 2 waves

// Per-CTA partial sums: [qb*NSB + sb][class][q] -- fully written, no init needed.
__device__ float g_part[(NQRY / QTILE) * NSB * NWAY * QTILE];

// ---------------- helpers ----------------------------------------------------
__device__ __forceinline__ uint32_t h2u(__half2 h) {
    return *reinterpret_cast<uint32_t*>(&h);
}
__device__ __forceinline__ uint32_t absdiff2(uint32_t q, __half2 s) {
    __half2 hq = *reinterpret_cast<__half2*>(&q);
    return h2u(__habs2(__hsub2(hq, s)));
}
__device__ __forceinline__ void mma16816(float* d, uint32_t a0, uint32_t a1,
                                         uint32_t a2, uint32_t a3,
                                         uint32_t b0, uint32_t b1) {
    asm volatile(
        "mma.sync.aligned.m16n8k16.row.col.f32.f16.f16.f32 "
        "{%0,%1,%2,%3}, {%4,%5,%6,%7}, {%8,%9}, {%0,%1,%2,%3};"
        : "+f"(d[0]), "+f"(d[1]), "+f"(d[2]), "+f"(d[3])
        : "r"(a0), "r"(a1), "r"(a2), "r"(a3), "r"(b0), "r"(b1));
}

// ---------------- main kernel (unchanged from R9/R10 -- HMMA-bound) -----------
__global__ __launch_bounds__(256, 1) void pairs_kernel(
    const float* __restrict__ qx, const float* __restrict__ sx,
    const float* __restrict__ W1, const float* __restrict__ b1,
    const float* __restrict__ w2v, const void* __restrict__ sy_raw) {
    __shared__ __half2 s_sm[SCHUNK * 64];          // s chunk, fp16x2
    __shared__ float   accf[2 * NWAY * QTILE];     // [nj][class][q]
    __shared__ int     slab[SCHUNK];
    __shared__ int     s_is64;

    const int tid  = threadIdx.x;
    const int lane = tid & 31;
    const int wid  = tid >> 5;
    const int mi   = wid & 3;
    const int nj   = wid >> 2;
    const int g    = lane >> 2;       // row-in-8 group
    const int i2   = lane & 3;        // k quad position
    const int q0   = blockIdx.x * QTILE;
    const int s0   = blockIdx.y * SCHUNK;
    const int ns   = min(SCHUNK, NSUP - s0);

    if (tid == 0) s_is64 = 1;
    for (int idx = tid; idx < 2 * NWAY * QTILE; idx += 256) accf[idx] = 0.0f;
    __syncthreads();

    // int64-vs-int32 detection for support_y (odd words all zero => int64).
    const int* sy32 = (const int*)sy_raw;
    if (sy32[2 * tid + 1] != 0) atomicExch(&s_is64, 0);

    // Stage s chunk as half2 (row = 64 half2 = 256B).
    for (int idx = tid; idx < ns * 64; idx += 256) {
        int r = idx >> 6, c = idx & 63;
        float2 v = *(const float2*)(sx + (size_t)(s0 + r) * DDIM + 2 * c);
        s_sm[idx] = __floats2half2_rn(v.x, v.y);
    }
    __syncthreads();

    const int is64 = s_is64;
    const long long* sy64 = (const long long*)sy_raw;
    if (tid < ns) slab[tid] = is64 ? (int)sy64[s0 + tid] : sy32[s0 + tid];

    // ---- q fragment values in registers: qh[ri][kb][h] ----
    uint32_t qh[4][8][2];
#pragma unroll
    for (int ri = 0; ri < 4; ++ri) {
        const float* qp = qx + (size_t)(q0 + mi * 32 + g + ri * 8) * DDIM + i2 * 2;
#pragma unroll
        for (int kb = 0; kb < 8; ++kb) {
            float2 v0 = *(const float2*)(qp + kb * 16);
            float2 v1 = *(const float2*)(qp + kb * 16 + 8);
            qh[ri][kb][0] = h2u(__floats2half2_rn(v0.x, v0.y));
            qh[ri][kb][1] = h2u(__floats2half2_rn(v1.x, v1.y));
        }
    }

    // ---- W1 B-fragments in registers (warp covers cols nj*32..+31) ----
    uint32_t Bf[4][8][2];
#pragma unroll
    for (int nb = 0; nb < 4; ++nb) {
        const float* wr = W1 + (size_t)(nj * 32 + nb * 8 + g) * DDIM + i2 * 2;
#pragma unroll
        for (int kb = 0; kb < 8; ++kb) {
            float2 v0 = *(const float2*)(wr + kb * 16);
            float2 v1 = *(const float2*)(wr + kb * 16 + 8);
            Bf[nb][kb][0] = h2u(__floats2half2_rn(v0.x, v0.y));
            Bf[nb][kb][1] = h2u(__floats2half2_rn(v1.x, v1.y));
        }
    }

    // ---- b1 / w2 for this thread's output columns ----
    float b1r[8], w2r[8];
#pragma unroll
    for (int nb = 0; nb < 4; ++nb)
#pragma unroll
        for (int c = 0; c < 2; ++c) {
            int col = nj * 32 + nb * 8 + i2 * 2 + c;
            b1r[nb * 2 + c] = b1[col];
            w2r[nb * 2 + c] = w2v[col];
        }

    __syncthreads();   // slab ready (s_sm already synced)

    // ---- main loop: one s row per iteration; no barriers inside ----
    for (int i = 0; i < ns; ++i) {
        const __half2* srow = s_sm + i * 64;

        float D[2][4][4];
#pragma unroll
        for (int mb = 0; mb < 2; ++mb)
#pragma unroll
            for (int nb = 0; nb < 4; ++nb) {
                D[mb][nb][0] = b1r[nb * 2];
                D[mb][nb][1] = b1r[nb * 2 + 1];
                D[mb][nb][2] = b1r[nb * 2];
                D[mb][nb][3] = b1r[nb * 2 + 1];
            }

#pragma unroll
        for (int kb = 0; kb < 8; ++kb) {
            __half2 hs0 = srow[kb * 8 + i2];
            __half2 hs1 = srow[kb * 8 + 4 + i2];
#pragma unroll
            for (int mb = 0; mb < 2; ++mb) {
                uint32_t a0 = absdiff2(qh[2 * mb][kb][0], hs0);
                uint32_t a1 = absdiff2(qh[2 * mb + 1][kb][0], hs0);
                uint32_t a2 = absdiff2(qh[2 * mb][kb][1], hs1);
                uint32_t a3 = absdiff2(qh[2 * mb + 1][kb][1], hs1);
#pragma unroll
                for (int nb = 0; nb < 4; ++nb)
                    mma16816(D[mb][nb], a0, a1, a2, a3, Bf[nb][kb][0], Bf[nb][kb][1]);
            }
        }

        // Epilogue: sim contribution = sum_n relu(h) * w2 for this warp slice.
        const int lab = slab[i];
#pragma unroll
        for (int mb = 0; mb < 2; ++mb) {
            float p0 = 0.0f, p1 = 0.0f;
#pragma unroll
            for (int nb = 0; nb < 4; ++nb)
#pragma unroll
                for (int c = 0; c < 2; ++c) {
                    p0 = fmaf(fmaxf(D[mb][nb][c],     0.0f), w2r[nb * 2 + c], p0);
                    p1 = fmaf(fmaxf(D[mb][nb][2 + c], 0.0f), w2r[nb * 2 + c], p1);
                }
            p0 += __shfl_xor_sync(0xffffffffu, p0, 1);
            p0 += __shfl_xor_sync(0xffffffffu, p0, 2);
            p1 += __shfl_xor_sync(0xffffffffu, p1, 1);
            p1 += __shfl_xor_sync(0xffffffffu, p1, 2);
            if (i2 == 0) {
                int r0 = mi * 32 + mb * 16 + g;
                accf[nj * (NWAY * QTILE) + lab * QTILE + r0]     += p0;
                accf[nj * (NWAY * QTILE) + lab * QTILE + r0 + 8] += p1;
            }
        }
    }

    __syncthreads();
    // Flush per-CTA partials (merge n-halves); unique g_part slice per CTA.
    float* dst = g_part + (size_t)(blockIdx.x * NSB + blockIdx.y) * (NWAY * QTILE);
    for (int idx = tid; idx < NWAY * QTILE; idx += 256)
        dst[idx] = accf[idx] + accf[NWAY * QTILE + idx];
}

// ---------------- finalize: 128 CTAs, sb split 4-ways + histogram + softmax --
// CTA handles 8 q values. Thread (quarter, c, qi): reduces <=10 sb partials for
// (q = blk*8 + qi, class c). Histogram of labels done warp-parallel in the same
// CTA (loads issued after the partial loads, so latencies overlap).
__global__ __launch_bounds__(256, 4) void finalize_kernel(
    float* __restrict__ out, const float* __restrict__ b2,
    const void* __restrict__ sy_raw) {
    __shared__ float s_part[4][NWAY][8];
    __shared__ float s_hist[8][NWAY];
    __shared__ float s_l[8][NWAY];
    __shared__ int   s_is64;

    const int tid  = threadIdx.x;
    const int lane = tid & 31;
    const int wid  = tid >> 5;
    const int quarter = tid >> 6;      // 0..3 (sb split)
    const int rem     = tid & 63;
    const int c       = rem >> 3;      // class 0..7
    const int qi      = rem & 7;       // q within CTA
    const int q  = blockIdx.x * 8 + qi;
    const int qb = q >> 7, qloc = q & 127;

    if (tid == 0) s_is64 = 1;
    __syncthreads();
    const int* sy32 = (const int*)sy_raw;
    if (sy32[2 * tid + 1] != 0 || sy32[2 * (tid + 256) + 1] != 0)
        atomicExch(&s_is64, 0);
    __syncthreads();
    const int is64 = s_is64;
    const long long* sy64 = (const long long*)sy_raw;

    // Partial reduction over this thread's sb range (<=10 independent loads).
    const int sb0 = quarter * 10;
    const int sb1 = (sb0 + 10 < NSB) ? sb0 + 10 : NSB;
    float acc = 0.0f;
    const float* p = g_part + ((size_t)(qb * NSB) * NWAY + c) * QTILE + qloc;
#pragma unroll 10
    for (int sb = sb0; sb < sb1; ++sb) acc += p[(size_t)sb * (NWAY * QTILE)];

    // Warp-parallel label histogram: warp w covers labels [w*128, w*128+128).
    float cnt[NWAY];
#pragma unroll
    for (int k = 0; k < NWAY; ++k) cnt[k] = 0.0f;
#pragma unroll
    for (int k = 0; k < 4; ++k) {
        int i = wid * 128 + k * 32 + lane;
        int lab = is64 ? (int)sy64[i] : sy32[i];
#pragma unroll
        for (int m = 0; m < NWAY; ++m) cnt[m] += (lab == m) ? 1.0f : 0.0f;
    }
#pragma unroll
    for (int m = 0; m < NWAY; ++m) {
        cnt[m] += __shfl_xor_sync(0xffffffffu, cnt[m], 16);
        cnt[m] += __shfl_xor_sync(0xffffffffu, cnt[m], 8);
        cnt[m] += __shfl_xor_sync(0xffffffffu, cnt[m], 4);
        cnt[m] += __shfl_xor_sync(0xffffffffu, cnt[m], 2);
        cnt[m] += __shfl_xor_sync(0xffffffffu, cnt[m], 1);
    }
    if (lane < NWAY) s_hist[wid][lane] = cnt[lane];

    s_part[quarter][c][qi] = acc;
    __syncthreads();

    // Combine quarters + counts -> logits.
    if (tid < 64) {
        float tot = s_part[0][c][qi] + s_part[1][c][qi] +
                    s_part[2][c][qi] + s_part[3][c][qi];
        float cn = 0.0f;
#pragma unroll
        for (int w = 0; w < 8; ++w) cn += s_hist[w][c];
        s_l[qi][c] = tot / cn + b2[0];
    }
    __syncthreads();

    // Threads 0..7: log_softmax for one q each.
    if (tid < 8) {
        float l[NWAY], mx = -1e30f;
#pragma unroll
        for (int k = 0; k < NWAY; ++k) {
            l[k] = s_l[tid][k];
            mx = fmaxf(mx, l[k]);
        }
        float s = 0.0f;
#pragma unroll
        for (int k = 0; k < NWAY; ++k) s += expf(l[k] - mx);
        const float ls = logf(s);
        float* o = out + (size_t)(blockIdx.x * 8 + tid) * NWAY;
#pragma unroll
        for (int k = 0; k < NWAY; ++k) o[k] = l[k] - mx - ls;
    }
}

// ---------------- launch --------------------------------------------------------
extern "C" void kernel_launch(void* const* d_in, const int* in_sizes, int n_in,
                              void* d_out, int out_size) {
    (void)in_sizes; (void)out_size;
    const float* support_x = (const float*)d_in[0];
    const void*  support_y = d_in[1];
    const float* query_x   = (const float*)d_in[2];
    int base = (n_in >= 8) ? 4 : 3;   // n_way scalar may or may not be marshalled
    const float* W1 = (const float*)d_in[base + 0];
    const float* b1 = (const float*)d_in[base + 1];
    const float* W2 = (const float*)d_in[base + 2];
    const float* b2 = (const float*)d_in[base + 3];
    float* out = (float*)d_out;

    pairs_kernel<<<dim3(NQRY / QTILE, NSB), 256>>>(query_x, support_x, W1, b1, W2,
                                                   support_y);
    finalize_kernel<<<NQRY / 8, 256>>>(out, b2, support_y);
}

// round 12
// speedup vs baseline: 9.2004x; 1.0655x over previous
#include <cuda_runtime.h>
#include <cuda_fp16.h>
#include <cstdint>
#include <math.h>

// Problem constants (fixed by setup_inputs).
#define NSUP   1024
#define NQRY   1024
#define DDIM   128
#define HDIM   64
#define NWAY   8
#define QTILE  128
#define SCHUNK 57
#define NSB    18           // ceil(1024/57); grid 8 x 18 = 144 CTAs = exactly 1 wave

// Per-CTA partial sums: [qb*NSB + sb][class][q] -- fully written, no init needed.
__device__ float g_part[(NQRY / QTILE) * NSB * NWAY * QTILE];
__device__ float g_counts[NWAY];     // written by pairs CTA (0,0)

// ---------------- helpers ----------------------------------------------------
__device__ __forceinline__ uint32_t h2u(__half2 h) {
    return *reinterpret_cast<uint32_t*>(&h);
}
__device__ __forceinline__ uint32_t absdiff2(uint32_t q, __half2 s) {
    __half2 hq = *reinterpret_cast<__half2*>(&q);
    return h2u(__habs2(__hsub2(hq, s)));
}
__device__ __forceinline__ void mma16816(float* d, uint32_t a0, uint32_t a1,
                                         uint32_t a2, uint32_t a3,
                                         uint32_t b0, uint32_t b1) {
    asm volatile(
        "mma.sync.aligned.m16n8k16.row.col.f32.f16.f16.f32 "
        "{%0,%1,%2,%3}, {%4,%5,%6,%7}, {%8,%9}, {%0,%1,%2,%3};"
        : "+f"(d[0]), "+f"(d[1]), "+f"(d[2]), "+f"(d[3])
        : "r"(a0), "r"(a1), "r"(a2), "r"(a3), "r"(b0), "r"(b1));
}

// ---------------- main kernel -------------------------------------------------
// CTA: 128-q block x 57-s chunk, grid 8x18 = one full wave. Warp (mi, nj):
// mi = 32-row m-slice, nj = 32-col n-slice. A fragments computed directly in
// registers (no smem A, no ldmatrix).
__global__ __launch_bounds__(256, 1) void pairs_kernel(
    const float* __restrict__ qx, const float* __restrict__ sx,
    const float* __restrict__ W1, const float* __restrict__ b1,
    const float* __restrict__ w2v, const void* __restrict__ sy_raw) {
    __shared__ __half2 s_sm[SCHUNK * 64];          // s chunk, fp16x2 (14.25KB)
    __shared__ float   accf[2 * NWAY * QTILE];     // [nj][class][q] (8KB)
    __shared__ int     slab[SCHUNK];
    __shared__ int     s_is64;

    const int tid  = threadIdx.x;
    const int lane = tid & 31;
    const int wid  = tid >> 5;
    const int mi   = wid & 3;
    const int nj   = wid >> 2;
    const int g    = lane >> 2;       // row-in-8 group
    const int i2   = lane & 3;        // k quad position
    const int q0   = blockIdx.x * QTILE;
    const int s0   = blockIdx.y * SCHUNK;
    const int ns   = min(SCHUNK, NSUP - s0);

    if (tid == 0) s_is64 = 1;
    for (int idx = tid; idx < 2 * NWAY * QTILE; idx += 256) accf[idx] = 0.0f;
    __syncthreads();

    // int64-vs-int32 detection for support_y (odd words all zero => int64).
    const int* sy32 = (const int*)sy_raw;
    if (sy32[2 * tid + 1] != 0) atomicExch(&s_is64, 0);

    // Stage s chunk as half2 (row = 64 half2 = 256B).
    for (int idx = tid; idx < ns * 64; idx += 256) {
        int r = idx >> 6, c = idx & 63;
        float2 v = *(const float2*)(sx + (size_t)(s0 + r) * DDIM + 2 * c);
        s_sm[idx] = __floats2half2_rn(v.x, v.y);
    }
    __syncthreads();

    const int is64 = s_is64;
    const long long* sy64 = (const long long*)sy_raw;
    for (int idx = tid; idx < ns; idx += 256)
        slab[idx] = is64 ? (int)sy64[s0 + idx] : sy32[s0 + idx];

    // ---- q fragment values in registers: qh[ri][kb][h] ----
    uint32_t qh[4][8][2];
#pragma unroll
    for (int ri = 0; ri < 4; ++ri) {
        const float* qp = qx + (size_t)(q0 + mi * 32 + g + ri * 8) * DDIM + i2 * 2;
#pragma unroll
        for (int kb = 0; kb < 8; ++kb) {
            float2 v0 = *(const float2*)(qp + kb * 16);
            float2 v1 = *(const float2*)(qp + kb * 16 + 8);
            qh[ri][kb][0] = h2u(__floats2half2_rn(v0.x, v0.y));
            qh[ri][kb][1] = h2u(__floats2half2_rn(v1.x, v1.y));
        }
    }

    // ---- W1 B-fragments in registers (warp covers cols nj*32..+31) ----
    uint32_t Bf[4][8][2];
#pragma unroll
    for (int nb = 0; nb < 4; ++nb) {
        const float* wr = W1 + (size_t)(nj * 32 + nb * 8 + g) * DDIM + i2 * 2;
#pragma unroll
        for (int kb = 0; kb < 8; ++kb) {
            float2 v0 = *(const float2*)(wr + kb * 16);
            float2 v1 = *(const float2*)(wr + kb * 16 + 8);
            Bf[nb][kb][0] = h2u(__floats2half2_rn(v0.x, v0.y));
            Bf[nb][kb][1] = h2u(__floats2half2_rn(v1.x, v1.y));
        }
    }

    // ---- b1 / w2 for this thread's output columns ----
    float b1r[8], w2r[8];
#pragma unroll
    for (int nb = 0; nb < 4; ++nb)
#pragma unroll
        for (int c = 0; c < 2; ++c) {
            int col = nj * 32 + nb * 8 + i2 * 2 + c;
            b1r[nb * 2 + c] = b1[col];
            w2r[nb * 2 + c] = w2v[col];
        }

    __syncthreads();   // slab ready (s_sm already synced)

    // ---- main loop: one s row per iteration; no barriers inside ----
    for (int i = 0; i < ns; ++i) {
        const __half2* srow = s_sm + i * 64;

        float D[2][4][4];
#pragma unroll
        for (int mb = 0; mb < 2; ++mb)
#pragma unroll
            for (int nb = 0; nb < 4; ++nb) {
                D[mb][nb][0] = b1r[nb * 2];
                D[mb][nb][1] = b1r[nb * 2 + 1];
                D[mb][nb][2] = b1r[nb * 2];
                D[mb][nb][3] = b1r[nb * 2 + 1];
            }

#pragma unroll
        for (int kb = 0; kb < 8; ++kb) {
            __half2 hs0 = srow[kb * 8 + i2];
            __half2 hs1 = srow[kb * 8 + 4 + i2];
#pragma unroll
            for (int mb = 0; mb < 2; ++mb) {
                uint32_t a0 = absdiff2(qh[2 * mb][kb][0], hs0);
                uint32_t a1 = absdiff2(qh[2 * mb + 1][kb][0], hs0);
                uint32_t a2 = absdiff2(qh[2 * mb][kb][1], hs1);
                uint32_t a3 = absdiff2(qh[2 * mb + 1][kb][1], hs1);
#pragma unroll
                for (int nb = 0; nb < 4; ++nb)
                    mma16816(D[mb][nb], a0, a1, a2, a3, Bf[nb][kb][0], Bf[nb][kb][1]);
            }
        }

        // Epilogue: sim contribution = sum_n relu(h) * w2 for this warp slice.
        const int lab = slab[i];
#pragma unroll
        for (int mb = 0; mb < 2; ++mb) {
            float p0 = 0.0f, p1 = 0.0f;
#pragma unroll
            for (int nb = 0; nb < 4; ++nb)
#pragma unroll
                for (int c = 0; c < 2; ++c) {
                    p0 = fmaf(fmaxf(D[mb][nb][c],     0.0f), w2r[nb * 2 + c], p0);
                    p1 = fmaf(fmaxf(D[mb][nb][2 + c], 0.0f), w2r[nb * 2 + c], p1);
                }
            p0 += __shfl_xor_sync(0xffffffffu, p0, 1);
            p0 += __shfl_xor_sync(0xffffffffu, p0, 2);
            p1 += __shfl_xor_sync(0xffffffffu, p1, 1);
            p1 += __shfl_xor_sync(0xffffffffu, p1, 2);
            if (i2 == 0) {
                int r0 = mi * 32 + mb * 16 + g;
                accf[nj * (NWAY * QTILE) + lab * QTILE + r0]     += p0;
                accf[nj * (NWAY * QTILE) + lab * QTILE + r0 + 8] += p1;
            }
        }
    }

    __syncthreads();
    // Flush per-CTA partials (merge n-halves); unique g_part slice per CTA.
    float* dst = g_part + (size_t)(blockIdx.x * NSB + blockIdx.y) * (NWAY * QTILE);
    for (int idx = tid; idx < NWAY * QTILE; idx += 256)
        dst[idx] = accf[idx] + accf[NWAY * QTILE + idx];

    // CTA (0,0), warp 0: label histogram -> g_counts (finalize runs after us).
    if (blockIdx.x == 0 && blockIdx.y == 0 && wid == 0) {
        float cnt[NWAY];
#pragma unroll
        for (int m = 0; m < NWAY; ++m) cnt[m] = 0.0f;
#pragma unroll 4
        for (int k = 0; k < 32; ++k) {
            int i = k * 32 + lane;
            int lab = is64 ? (int)sy64[i] : sy32[i];
#pragma unroll
            for (int m = 0; m < NWAY; ++m) cnt[m] += (lab == m) ? 1.0f : 0.0f;
        }
#pragma unroll
        for (int m = 0; m < NWAY; ++m) {
            cnt[m] += __shfl_xor_sync(0xffffffffu, cnt[m], 16);
            cnt[m] += __shfl_xor_sync(0xffffffffu, cnt[m], 8);
            cnt[m] += __shfl_xor_sync(0xffffffffu, cnt[m], 4);
            cnt[m] += __shfl_xor_sync(0xffffffffu, cnt[m], 2);
            cnt[m] += __shfl_xor_sync(0xffffffffu, cnt[m], 1);
        }
        if (lane < NWAY) g_counts[lane] = cnt[lane];
    }
}

// ---------------- finalize: pure parallel reduction + softmax ----------------
// 128 CTAs x 256 threads; CTA handles 8 q. Thread (quarter, c, qi) reduces <=5
// sb partials for (q = blk*8 + qi, class c). Counts precomputed in pairs.
__global__ __launch_bounds__(256, 4) void finalize_kernel(
    float* __restrict__ out, const float* __restrict__ b2) {
    __shared__ float s_part[4][NWAY][8];
    __shared__ float s_l[8][NWAY];

    const int tid     = threadIdx.x;
    const int quarter = tid >> 6;      // 0..3 (sb split: 5,5,5,3)
    const int rem     = tid & 63;
    const int c       = rem >> 3;      // class 0..7
    const int qi      = rem & 7;       // q within CTA
    const int q  = blockIdx.x * 8 + qi;
    const int qb = q >> 7, qloc = q & 127;

    const int sb0 = quarter * 5;
    const int sb1 = (sb0 + 5 < NSB) ? sb0 + 5 : NSB;
    float acc = 0.0f;
    const float* p = g_part + ((size_t)(qb * NSB) * NWAY + c) * QTILE + qloc;
#pragma unroll 5
    for (int sb = sb0; sb < sb1; ++sb) acc += p[(size_t)sb * (NWAY * QTILE)];

    s_part[quarter][c][qi] = acc;
    __syncthreads();

    if (tid < 64) {
        float tot = s_part[0][c][qi] + s_part[1][c][qi] +
                    s_part[2][c][qi] + s_part[3][c][qi];
        s_l[qi][c] = tot / g_counts[c] + b2[0];
    }
    __syncthreads();

    if (tid < 8) {
        float l[NWAY], mx = -1e30f;
#pragma unroll
        for (int k = 0; k < NWAY; ++k) {
            l[k] = s_l[tid][k];
            mx = fmaxf(mx, l[k]);
        }
        float s = 0.0f;
#pragma unroll
        for (int k = 0; k < NWAY; ++k) s += expf(l[k] - mx);
        const float ls = logf(s);
        float* o = out + (size_t)(blockIdx.x * 8 + tid) * NWAY;
#pragma unroll
        for (int k = 0; k < NWAY; ++k) o[k] = l[k] - mx - ls;
    }
}

// ---------------- launch --------------------------------------------------------
extern "C" void kernel_launch(void* const* d_in, const int* in_sizes, int n_in,
                              void* d_out, int out_size) {
    (void)in_sizes; (void)out_size;
    const float* support_x = (const float*)d_in[0];
    const void*  support_y = d_in[1];
    const float* query_x   = (const float*)d_in[2];
    int base = (n_in >= 8) ? 4 : 3;   // n_way scalar may or may not be marshalled
    const float* W1 = (const float*)d_in[base + 0];
    const float* b1 = (const float*)d_in[base + 1];
    const float* W2 = (const float*)d_in[base + 2];
    const float* b2 = (const float*)d_in[base + 3];
    float* out = (float*)d_out;

    pairs_kernel<<<dim3(NQRY / QTILE, NSB), 256>>>(query_x, support_x, W1, b1, W2,
                                                   support_y);
    finalize_kernel<<<NQRY / 8, 256>>>(out, b2);
}